// round 3
// baseline (speedup 1.0000x reference)
#include <cuda_runtime.h>

constexpr int NB  = 8;
constexpr int NS  = 4096;
constexpr int ND  = 512;
constexpr int NH  = 4;
constexpr int DH  = 64;
constexpr int NI  = 256;   // NH*DH
constexpr int NM  = 256;   // landmarks
constexpr int NBH = 32;    // NB*NH
constexpr int KW  = 33;

// ---------------- scratch (device globals; allocation-free rule) -----------
__device__ float g_xn[(size_t)NB*NS*ND];
__device__ float g_q [(size_t)NBH*NS*DH];
__device__ float g_k [(size_t)NBH*NS*DH];
__device__ float g_v [(size_t)NBH*NS*DH];
__device__ float g_ql[NBH*NM*DH];
__device__ float g_kl[NBH*NM*DH];
__device__ float g_a1[(size_t)NBH*NS*NM];
__device__ float g_a2[NBH*NM*NM];
__device__ float g_za[NBH*NM*NM];
__device__ float g_zb[NBH*NM*NM];
__device__ float g_xz[NBH*NM*NM];
__device__ float g_t1[NBH*NM*NM];
__device__ float g_t2[NBH*NM*NM];
__device__ float g_w3[NBH*NM*DH];
__device__ float g_u [NBH*NM*DH];
__device__ float g_oh[(size_t)NB*NS*NI];
__device__ unsigned g_red[2];

__global__ void init_red_kernel() { g_red[0] = 0u; g_red[1] = 0u; }

// ---------------- LayerNorm: one block per row of 512 ----------------------
__global__ __launch_bounds__(128) void ln_kernel(
    const float* __restrict__ x, const float* __restrict__ g,
    const float* __restrict__ b)
{
    int row = blockIdx.x;
    int t = threadIdx.x;
    float4 v4 = reinterpret_cast<const float4*>(x + (size_t)row*ND)[t];
    float s = v4.x + v4.y + v4.z + v4.w;
    __shared__ float r1[4], r2[4];
#pragma unroll
    for (int o = 16; o > 0; o >>= 1) s += __shfl_xor_sync(0xffffffffu, s, o);
    if ((t & 31) == 0) r1[t >> 5] = s;
    __syncthreads();
    float mu = (r1[0] + r1[1] + r1[2] + r1[3]) * (1.0f / ND);
    float dx = v4.x - mu, dy = v4.y - mu, dz = v4.z - mu, dw = v4.w - mu;
    float ss = dx*dx + dy*dy + dz*dz + dw*dw;
#pragma unroll
    for (int o = 16; o > 0; o >>= 1) ss += __shfl_xor_sync(0xffffffffu, ss, o);
    if ((t & 31) == 0) r2[t >> 5] = ss;
    __syncthreads();
    float var = (r2[0] + r2[1] + r2[2] + r2[3]) * (1.0f / ND);
    float inv = rsqrtf(var + 1e-5f);
    float4 gv = reinterpret_cast<const float4*>(g)[t];
    float4 bv = reinterpret_cast<const float4*>(b)[t];
    float4 o4;
    o4.x = dx*inv*gv.x + bv.x;
    o4.y = dy*inv*gv.y + bv.y;
    o4.z = dz*inv*gv.z + bv.z;
    o4.w = dw*inv*gv.w + bv.w;
    reinterpret_cast<float4*>(g_xn + (size_t)row*ND)[t] = o4;
}

// ---------------- QKV GEMM [32768,512]x[512,768] -> head layout ------------
__global__ __launch_bounds__(256) void qkv_gemm_kernel(const float* __restrict__ W)
{
    __shared__ __align__(16) float As[16][68];
    __shared__ __align__(16) float Bs[16][64];
    int tid = threadIdx.x;
    int n0 = blockIdx.x * 64;
    int m0 = blockIdx.y * 64;
    int alm = tid >> 2, alk = (tid & 3) << 2;
    int blk = tid >> 4, bln = (tid & 15) << 2;
    int ty = tid >> 4, tx = tid & 15;
    float acc[4][4];
#pragma unroll
    for (int i = 0; i < 4; i++)
#pragma unroll
        for (int j = 0; j < 4; j++) acc[i][j] = 0.f;

    for (int k0 = 0; k0 < ND; k0 += 16) {
        float4 a4 = *reinterpret_cast<const float4*>(g_xn + (size_t)(m0+alm)*ND + k0 + alk);
        As[alk+0][alm] = a4.x; As[alk+1][alm] = a4.y;
        As[alk+2][alm] = a4.z; As[alk+3][alm] = a4.w;
        *reinterpret_cast<float4*>(&Bs[blk][bln]) =
            *reinterpret_cast<const float4*>(W + (size_t)(k0+blk)*768 + n0 + bln);
        __syncthreads();
#pragma unroll
        for (int kk = 0; kk < 16; kk++) {
            float4 ar = *reinterpret_cast<const float4*>(&As[kk][ty << 2]);
            float4 br = *reinterpret_cast<const float4*>(&Bs[kk][tx << 2]);
            float a_[4] = {ar.x, ar.y, ar.z, ar.w};
            float b_[4] = {br.x, br.y, br.z, br.w};
#pragma unroll
            for (int i = 0; i < 4; i++)
#pragma unroll
                for (int j = 0; j < 4; j++) acc[i][j] += a_[i] * b_[j];
        }
        __syncthreads();
    }
#pragma unroll
    for (int i = 0; i < 4; i++) {
        int row = m0 + (ty << 2) + i;
        int bb = row >> 12;
        int n = row & (NS - 1);
#pragma unroll
        for (int j = 0; j < 4; j++) {
            int col = n0 + (tx << 2) + j;
            int part = col >> 8;
            int e = col & 255;
            int h = e >> 6, d = e & 63;
            float val = acc[i][j];
            float* dst = (part == 0) ? g_q : (part == 1) ? g_k : g_v;
            if (part == 0) val *= 0.125f;  // dh^-0.5
            dst[(((size_t)bb*NH + h)*NS + n)*DH + d] = val;
        }
    }
}

// ---------------- landmark means (groups of 16) -----------------------------
__global__ void landmark_kernel(const float* __restrict__ src, float* __restrict__ dst)
{
    int idx = blockIdx.x * blockDim.x + threadIdx.x;
    int d = idx & 63;
    int j = (idx >> 6) & (NM - 1);
    int bh = idx >> 14;
    const float* p = src + ((size_t)bh*NS + (size_t)j*16)*DH + d;
    float s = 0.f;
#pragma unroll
    for (int i = 0; i < 16; i++) s += p[(size_t)i*DH];
    dst[idx] = s * (1.0f / 16.0f);
}

// ---------------- fused A@B^T + row softmax over 256 ------------------------
// A:[Ma,64] rows per bh, B:[256,64] (kl). 16 rows per block, 256 threads.
__global__ __launch_bounds__(256) void attn_sm256_kernel(
    const float* __restrict__ A, const float* __restrict__ Bm,
    float* __restrict__ O, int Ma)
{
    __shared__ __align__(16) float Qs[16][64];
    __shared__ float Bs[64][65];
    __shared__ __align__(16) float Ss[16][256];
    int bh = blockIdx.y;
    int r0 = blockIdx.x * 16;
    const float* Ab = A + (size_t)bh*Ma*DH;
    const float* Bb = Bm + (size_t)bh*NM*DH;
    float* Ob = O + (size_t)bh*Ma*NM;
    int t = threadIdx.x;
    {
        int rr = t >> 4, c4 = (t & 15) << 2;
        *reinterpret_cast<float4*>(&Qs[rr][c4]) =
            *reinterpret_cast<const float4*>(Ab + (size_t)(r0+rr)*DH + c4);
    }
    int row = t >> 4, cb0 = t & 15;
    float acc[16];
    for (int cb = 0; cb < 4; cb++) {
        __syncthreads();
#pragma unroll
        for (int i = 0; i < 4; i++) {
            int fi = i*256 + t;
            int rr = fi >> 4, c4 = (fi & 15) << 2;
            float4 bv = *reinterpret_cast<const float4*>(Bb + (size_t)(cb*64+rr)*DH + c4);
            Bs[rr][c4+0] = bv.x; Bs[rr][c4+1] = bv.y;
            Bs[rr][c4+2] = bv.z; Bs[rr][c4+3] = bv.w;
        }
        __syncthreads();
        float a0 = 0, a1 = 0, a2 = 0, a3 = 0;
#pragma unroll
        for (int k = 0; k < 64; k++) {
            float a = Qs[row][k];
            a0 += a * Bs[cb0     ][k];
            a1 += a * Bs[cb0 + 16][k];
            a2 += a * Bs[cb0 + 32][k];
            a3 += a * Bs[cb0 + 48][k];
        }
        acc[cb*4+0] = a0; acc[cb*4+1] = a1; acc[cb*4+2] = a2; acc[cb*4+3] = a3;
    }
    float mx = acc[0];
#pragma unroll
    for (int i = 1; i < 16; i++) mx = fmaxf(mx, acc[i]);
#pragma unroll
    for (int o = 8; o > 0; o >>= 1) mx = fmaxf(mx, __shfl_xor_sync(0xffffffffu, mx, o));
    float sum = 0.f;
#pragma unroll
    for (int i = 0; i < 16; i++) { acc[i] = __expf(acc[i] - mx); sum += acc[i]; }
#pragma unroll
    for (int o = 8; o > 0; o >>= 1) sum += __shfl_xor_sync(0xffffffffu, sum, o);
    float inv = 1.0f / sum;
#pragma unroll
    for (int i = 0; i < 16; i++) Ss[row][cb0 + 16*i] = acc[i] * inv;
    __syncthreads();
#pragma unroll
    for (int i = 0; i < 4; i++) {
        int fi = i*256 + t;
        int rr = fi >> 6, c4 = (fi & 63) << 2;
        *reinterpret_cast<float4*>(Ob + (size_t)(r0+rr)*NM + c4) =
            *reinterpret_cast<const float4*>(&Ss[rr][c4]);
    }
}

// ---------------- flash: w3 = softmax(ql @ k^T) @ v -------------------------
__global__ __launch_bounds__(256) void sim3_flash_kernel()
{
    __shared__ __align__(16) float Qs[16][64];
    __shared__ float Ks[64][65];
    __shared__ float Vs[64][65];
    __shared__ float Ps[16][64];
    int bh = blockIdx.y;
    int r0 = blockIdx.x * 16;
    const float* Qb = g_ql + ((size_t)bh*NM + r0)*DH;
    const float* Kb = g_k + (size_t)bh*NS*DH;
    const float* Vb = g_v + (size_t)bh*NS*DH;
    int t = threadIdx.x;
    int row = t >> 4, ln = t & 15;
    {
        int rr = t >> 4, c4 = (t & 15) << 2;
        *reinterpret_cast<float4*>(&Qs[rr][c4]) =
            *reinterpret_cast<const float4*>(Qb + (size_t)rr*DH + c4);
    }
    float Oa[4] = {0, 0, 0, 0};
    float mrun = -1e30f, lrun = 0.f;
    for (int kt = 0; kt < NS/64; kt++) {
        __syncthreads();
#pragma unroll
        for (int i = 0; i < 4; i++) {
            int fi = i*256 + t;
            int rr = fi >> 4, c4 = (fi & 15) << 2;
            float4 kv = *reinterpret_cast<const float4*>(Kb + (size_t)(kt*64+rr)*DH + c4);
            Ks[rr][c4+0] = kv.x; Ks[rr][c4+1] = kv.y; Ks[rr][c4+2] = kv.z; Ks[rr][c4+3] = kv.w;
            float4 vv = *reinterpret_cast<const float4*>(Vb + (size_t)(kt*64+rr)*DH + c4);
            Vs[rr][c4+0] = vv.x; Vs[rr][c4+1] = vv.y; Vs[rr][c4+2] = vv.z; Vs[rr][c4+3] = vv.w;
        }
        __syncthreads();
        float s0 = 0, s1 = 0, s2 = 0, s3 = 0;
#pragma unroll
        for (int k = 0; k < 64; k++) {
            float a = Qs[row][k];
            s0 += a * Ks[ln     ][k];
            s1 += a * Ks[ln + 16][k];
            s2 += a * Ks[ln + 32][k];
            s3 += a * Ks[ln + 48][k];
        }
        float tm = fmaxf(fmaxf(s0, s1), fmaxf(s2, s3));
#pragma unroll
        for (int o = 8; o > 0; o >>= 1) tm = fmaxf(tm, __shfl_xor_sync(0xffffffffu, tm, o));
        float newm = fmaxf(mrun, tm);
        float corr = __expf(mrun - newm);
        float p0 = __expf(s0 - newm), p1 = __expf(s1 - newm);
        float p2 = __expf(s2 - newm), p3 = __expf(s3 - newm);
        Ps[row][ln] = p0; Ps[row][ln+16] = p1; Ps[row][ln+32] = p2; Ps[row][ln+48] = p3;
        float ps = p0 + p1 + p2 + p3;
#pragma unroll
        for (int o = 8; o > 0; o >>= 1) ps += __shfl_xor_sync(0xffffffffu, ps, o);
        lrun = lrun * corr + ps;
        mrun = newm;
#pragma unroll
        for (int j = 0; j < 4; j++) Oa[j] *= corr;
        __syncthreads();
#pragma unroll
        for (int c = 0; c < 64; c++) {
            float p = Ps[row][c];
            Oa[0] += p * Vs[c][ln];
            Oa[1] += p * Vs[c][ln + 16];
            Oa[2] += p * Vs[c][ln + 32];
            Oa[3] += p * Vs[c][ln + 48];
        }
    }
    float invl = 1.0f / lrun;
    float* Wb = g_w3 + ((size_t)bh*NM + r0 + row)*DH;
    Wb[ln]      = Oa[0] * invl;
    Wb[ln + 16] = Oa[1] * invl;
    Wb[ln + 32] = Oa[2] * invl;
    Wb[ln + 48] = Oa[3] * invl;
}

// ---------------- pinv prep: global max row-sum / col-sum of a2 -------------
__global__ void pinv_prep_kernel()
{
    int i = blockIdx.x * blockDim.x + threadIdx.x;  // 8192
    int bh = i >> 8, r = i & 255;
    const float* A = g_a2 + (size_t)bh*NM*NM;
    float rs = 0.f, cs = 0.f;
    for (int j = 0; j < NM; j++) { rs += A[(size_t)r*NM + j]; cs += A[(size_t)j*NM + r]; }
    atomicMax(&g_red[0], __float_as_uint(rs));
    atomicMax(&g_red[1], __float_as_uint(cs));
}

__global__ void zinit_kernel()
{
    float denom = __uint_as_float(g_red[0]) * __uint_as_float(g_red[1]);
    float inv = 1.0f / denom;
    int idx = blockIdx.x * blockDim.x + threadIdx.x;  // 2M
    int j = idx & 255, i = (idx >> 8) & 255, bh = idx >> 16;
    g_za[idx] = g_a2[((size_t)bh*NM + j)*NM + i] * inv;
}

// ---------------- generic batched GEMM (row-major NN), 64x64x16 -------------
// C = scl*(sCoef*(A@B) + aCoef*A)  [+ C if accum]
// A base = A + bh*sA (row stride K); B base = B + bh*sB (row stride Ncols)
// C base = C + (bh/hdiv)*cOuter + (bh%hdiv)*cInner (row stride rsC)
__global__ __launch_bounds__(256) void gemm_nn_kernel(
    const float* __restrict__ A, const float* __restrict__ Bm, float* __restrict__ C,
    int M, int Ncols, int K,
    long long sA, long long sB,
    long long cOuter, long long cInner, int hdiv, int rsC,
    float aCoef, float sCoef, float scl, int accum)
{
    __shared__ __align__(16) float As[16][68];
    __shared__ __align__(16) float Bs[16][64];
    int bh = blockIdx.z;
    const float* Ab = A + (size_t)bh * sA;
    const float* Bb = Bm + (size_t)bh * sB;
    float* Cb = C + (size_t)(bh / hdiv) * cOuter + (size_t)(bh % hdiv) * cInner;
    int n0 = blockIdx.x * 64, m0 = blockIdx.y * 64;
    int tid = threadIdx.x;
    int alm = tid >> 2, alk = (tid & 3) << 2;
    int blk = tid >> 4, bln = (tid & 15) << 2;
    int ty = tid >> 4, tx = tid & 15;
    float acc[4][4];
#pragma unroll
    for (int i = 0; i < 4; i++)
#pragma unroll
        for (int j = 0; j < 4; j++) acc[i][j] = 0.f;

    for (int k0 = 0; k0 < K; k0 += 16) {
        float4 a4 = *reinterpret_cast<const float4*>(Ab + (size_t)(m0+alm)*K + k0 + alk);
        As[alk+0][alm] = a4.x; As[alk+1][alm] = a4.y;
        As[alk+2][alm] = a4.z; As[alk+3][alm] = a4.w;
        *reinterpret_cast<float4*>(&Bs[blk][bln]) =
            *reinterpret_cast<const float4*>(Bb + (size_t)(k0+blk)*Ncols + n0 + bln);
        __syncthreads();
#pragma unroll
        for (int kk = 0; kk < 16; kk++) {
            float4 ar = *reinterpret_cast<const float4*>(&As[kk][ty << 2]);
            float4 br = *reinterpret_cast<const float4*>(&Bs[kk][tx << 2]);
            float a_[4] = {ar.x, ar.y, ar.z, ar.w};
            float b_[4] = {br.x, br.y, br.z, br.w};
#pragma unroll
            for (int i = 0; i < 4; i++)
#pragma unroll
                for (int j = 0; j < 4; j++) acc[i][j] += a_[i] * b_[j];
        }
        __syncthreads();
    }
#pragma unroll
    for (int i = 0; i < 4; i++) {
        int r = m0 + (ty << 2) + i;
#pragma unroll
        for (int j = 0; j < 4; j++) {
            int c = n0 + (tx << 2) + j;
            float val = sCoef * acc[i][j];
            if (aCoef != 0.0f) val += aCoef * Ab[(size_t)r*K + c];
            val *= scl;
            float* p = Cb + (size_t)r*rsC + c;
            if (accum) val += *p;
            *p = val;
        }
    }
}

// ---------------- depthwise conv residual -> g_oh ---------------------------
__global__ void conv_kernel(const float* __restrict__ w)
{
    int idx = blockIdx.x * blockDim.x + threadIdx.x;  // NB*NS*NI
    int c = idx & 255;
    int n = (idx >> 8) & (NS - 1);
    int b = idx >> 20;
    int h = c >> 6, d = c & 63;
    const float* vb = g_v + ((size_t)(b*NH + h)*NS)*DH + d;
    float s = 0.f;
#pragma unroll
    for (int k = 0; k < KW; k++) {
        int nn = n + k - KW/2;
        if (nn >= 0 && nn < NS) s += w[h*KW + k] * vb[(size_t)nn*DH];
    }
    g_oh[idx] = s;
}

// ---------------- final projection: out = x + (oh @ W + b) ------------------
__global__ __launch_bounds__(256) void proj_kernel(
    const float* __restrict__ W, const float* __restrict__ bias,
    const float* __restrict__ x, float* __restrict__ out)
{
    __shared__ __align__(16) float As[16][68];
    __shared__ __align__(16) float Bs[16][64];
    int n0 = blockIdx.x * 64, m0 = blockIdx.y * 64;
    int tid = threadIdx.x;
    int alm = tid >> 2, alk = (tid & 3) << 2;
    int blk = tid >> 4, bln = (tid & 15) << 2;
    int ty = tid >> 4, tx = tid & 15;
    float acc[4][4];
#pragma unroll
    for (int i = 0; i < 4; i++)
#pragma unroll
        for (int j = 0; j < 4; j++) acc[i][j] = 0.f;

    for (int k0 = 0; k0 < NI; k0 += 16) {
        float4 a4 = *reinterpret_cast<const float4*>(g_oh + (size_t)(m0+alm)*NI + k0 + alk);
        As[alk+0][alm] = a4.x; As[alk+1][alm] = a4.y;
        As[alk+2][alm] = a4.z; As[alk+3][alm] = a4.w;
        *reinterpret_cast<float4*>(&Bs[blk][bln]) =
            *reinterpret_cast<const float4*>(W + (size_t)(k0+blk)*ND + n0 + bln);
        __syncthreads();
#pragma unroll
        for (int kk = 0; kk < 16; kk++) {
            float4 ar = *reinterpret_cast<const float4*>(&As[kk][ty << 2]);
            float4 br = *reinterpret_cast<const float4*>(&Bs[kk][tx << 2]);
            float a_[4] = {ar.x, ar.y, ar.z, ar.w};
            float b_[4] = {br.x, br.y, br.z, br.w};
#pragma unroll
            for (int i = 0; i < 4; i++)
#pragma unroll
                for (int j = 0; j < 4; j++) acc[i][j] += a_[i] * b_[j];
        }
        __syncthreads();
    }
#pragma unroll
    for (int i = 0; i < 4; i++) {
        int r = m0 + (ty << 2) + i;
#pragma unroll
        for (int j = 0; j < 4; j++) {
            int c = n0 + (tx << 2) + j;
            out[(size_t)r*ND + c] = acc[i][j] + bias[c] + x[(size_t)r*ND + c];
        }
    }
}

// ---------------- host launcher ---------------------------------------------
template <typename T>
static float* sym_addr(T& sym) {
    void* p = nullptr;
    cudaGetSymbolAddress(&p, sym);
    return reinterpret_cast<float*>(p);
}

extern "C" void kernel_launch(void* const* d_in, const int* in_sizes, int n_in,
                              void* d_out, int out_size)
{
    const float* x     = (const float*)d_in[0];
    const float* ln_g  = (const float*)d_in[1];
    const float* ln_b  = (const float*)d_in[2];
    const float* w_qkv = (const float*)d_in[3];
    const float* w_out = (const float*)d_in[4];
    const float* b_out = (const float*)d_in[5];
    const float* w_res = (const float*)d_in[6];
    float* out = (float*)d_out;

    float* p_q  = sym_addr(g_q);
    float* p_k  = sym_addr(g_k);
    float* p_v  = sym_addr(g_v);
    float* p_ql = sym_addr(g_ql);
    float* p_kl = sym_addr(g_kl);
    float* p_a1 = sym_addr(g_a1);
    float* p_a2 = sym_addr(g_a2);
    float* p_za = sym_addr(g_za);
    float* p_zb = sym_addr(g_zb);
    float* p_xz = sym_addr(g_xz);
    float* p_t1 = sym_addr(g_t1);
    float* p_t2 = sym_addr(g_t2);
    float* p_w3 = sym_addr(g_w3);
    float* p_u  = sym_addr(g_u);
    float* p_oh = sym_addr(g_oh);

    const long long SM2 = (long long)NM * NM;       // 65536
    const long long SW  = (long long)NM * DH;       // 16384

    // 1. LayerNorm
    ln_kernel<<<NB*NS, 128>>>(x, ln_g, ln_b);
    // 2. QKV
    qkv_gemm_kernel<<<dim3(12, (NB*NS)/64), 256>>>(w_qkv);
    // 3. Landmarks
    landmark_kernel<<<(NBH*NM*DH)/256, 256>>>(p_q, p_ql);
    landmark_kernel<<<(NBH*NM*DH)/256, 256>>>(p_k, p_kl);
    // 4. a1 = softmax(q @ kl^T), a2 = softmax(ql @ kl^T)
    attn_sm256_kernel<<<dim3(NS/16, NBH), 256>>>(p_q,  p_kl, p_a1, NS);
    attn_sm256_kernel<<<dim3(NM/16, NBH), 256>>>(p_ql, p_kl, p_a2, NM);
    // 5. w3 = softmax(ql @ k^T) @ v  (flash)
    sim3_flash_kernel<<<dim3(NM/16, NBH), 256>>>();
    // 6. pinv init
    init_red_kernel<<<1, 1>>>();
    pinv_prep_kernel<<<32, 256>>>();
    zinit_kernel<<<(NBH*NM*NM)/256, 256>>>();
    // 7. 6 Newton iterations (z in p_za; ping-pong)
    float* zc = p_za; float* zn = p_zb;
    dim3 gsq(4, 4, NBH);
    for (int it = 0; it < 6; it++) {
        gemm_nn_kernel<<<gsq, 256>>>(p_a2, zc,  p_xz, NM, NM, NM, SM2, SM2, SM2, 0, 1, NM, 0.f,  1.f, 1.f,   0);
        gemm_nn_kernel<<<gsq, 256>>>(p_xz, p_xz, p_t1, NM, NM, NM, SM2, SM2, SM2, 0, 1, NM, 7.f, -1.f, 1.f,   0);
        gemm_nn_kernel<<<gsq, 256>>>(p_xz, p_t1, p_t2, NM, NM, NM, SM2, SM2, SM2, 0, 1, NM, 15.f,-1.f, 1.f,   0);
        gemm_nn_kernel<<<gsq, 256>>>(zc,   p_t2, zn,   NM, NM, NM, SM2, SM2, SM2, 0, 1, NM, 13.f,-1.f, 0.25f, 0);
        float* tmp = zc; zc = zn; zn = tmp;
    }
    // 8. u = z @ w3   [256,256]x[256,64]
    gemm_nn_kernel<<<dim3(1, 4, NBH), 256>>>(zc, p_w3, p_u, NM, DH, NM, SM2, SW, SW, 0, 1, DH, 0.f, 1.f, 1.f, 0);
    // 9. conv residual into g_oh, then oh += a1 @ u
    conv_kernel<<<(NB*NS*NI)/256, 256>>>(w_res);
    gemm_nn_kernel<<<dim3(1, NS/64, NBH), 256>>>(
        p_a1, p_u, p_oh, NS, DH, NM,
        (long long)NS*NM, SW,
        (long long)NS*NI, (long long)DH, NH, NI,
        0.f, 1.f, 1.f, 1);
    // 10. out = x + (oh @ w_out + b_out)
    proj_kernel<<<dim3(ND/64, (NB*NS)/64), 256>>>(w_out, b_out, x, out);
}

// round 5
// speedup vs baseline: 1.3429x; 1.3429x over previous
#include <cuda_runtime.h>
#include <cuda_bf16.h>
#include <mma.h>
#include <cstdint>

using namespace nvcuda;

constexpr int NB  = 8;
constexpr int NS  = 4096;
constexpr int ND  = 512;
constexpr int NH  = 4;
constexpr int DH  = 64;
constexpr int NI  = 256;
constexpr int NM  = 256;
constexpr int NBH = 32;
constexpr int KW  = 33;

typedef __nv_bfloat16 bf16;

// ---------------- scratch ----------------------------------------------------
__device__ float g_q [(size_t)NBH*NS*DH];
__device__ float g_k [(size_t)NBH*NS*DH];
__device__ float g_v [(size_t)NBH*NS*DH];
__device__ float g_ql[NBH*NM*DH];
__device__ float g_kl[NBH*NM*DH];
__device__ float g_ohf[(size_t)NB*NS*NI];
__device__ unsigned g_red[2];

__device__ bf16 g_xnb [(size_t)NB*NS*ND];
__device__ bf16 g_wqkvT[768*512];
__device__ bf16 g_woutT[512*256];
__device__ bf16 g_a1b [(size_t)NBH*NS*NM];
__device__ bf16 g_a2b [NBH*NM*NM];
__device__ bf16 g_zA  [NBH*NM*NM];
__device__ bf16 g_zAT [NBH*NM*NM];
__device__ bf16 g_zB  [NBH*NM*NM];
__device__ bf16 g_zBT [NBH*NM*NM];
__device__ bf16 g_xz  [NBH*NM*NM];
__device__ bf16 g_xzT [NBH*NM*NM];
__device__ bf16 g_t1T [NBH*NM*NM];
__device__ bf16 g_t2T [NBH*NM*NM];
__device__ bf16 g_w3T [NBH*DH*NM];
__device__ bf16 g_uT  [NBH*DH*NM];
__device__ bf16 g_ohb [(size_t)NB*NS*NI];

__device__ __forceinline__ uint32_t pack_bf2(float a, float b) {
    __nv_bfloat162 h = __floats2bfloat162_rn(a, b);
    return *reinterpret_cast<uint32_t*>(&h);
}

// ============================================================================
// wmma bf16 GEMM: D[128,64] tile = A[M,K] @ BT[N,K]^T, fp32 accum.
// 256 threads = 8 warps, warp tile 32x32 (2x2 wmma 16x16x16), BK=32.
// Shared: As 128x48 bf16, Bs 64x48 bf16; epilogue reuses smem as Cs 128x72 f32.
// ============================================================================
constexpr int LDA = 48;              // bf16 elements (96B, 32B-aligned rows)
constexpr int LDC = 72;              // f32 elements (288B rows)
constexpr int GEMM_DSMEM = 128*LDC*4;   // 36864 >= (128+64)*48*2

__global__ __launch_bounds__(256) void gemm_wmma(
    const bf16* __restrict__ A, const bf16* __restrict__ BT,
    int K, long long sA, long long sB,
    int mode, float aCoef, float sCoef, float scl,
    bf16* outb, bf16* outbT, float* __restrict__ outf,
    const float* __restrict__ bias, const float* __restrict__ xres)
{
    extern __shared__ __align__(32) char smem[];
    bf16* As = reinterpret_cast<bf16*>(smem);
    bf16* Bs = As + 128*LDA;
    float* Cs = reinterpret_cast<float*>(smem);

    int tid = threadIdx.x, wid = tid >> 5;
    int bz = blockIdx.z;
    const bf16* Ab = A  + (size_t)bz * sA;
    const bf16* Bb = BT + (size_t)bz * sB;
    int n0 = blockIdx.x * 64, m0 = blockIdx.y * 128;
    int wm = (wid & 3) * 32, wn = (wid >> 2) * 32;

    wmma::fragment<wmma::accumulator, 16, 16, 16, float> acc[2][2];
#pragma unroll
    for (int i = 0; i < 2; i++)
#pragma unroll
        for (int j = 0; j < 2; j++) wmma::fill_fragment(acc[i][j], 0.0f);

    for (int k0 = 0; k0 < K; k0 += 32) {
        __syncthreads();
#pragma unroll
        for (int i = 0; i < 2; i++) {              // A: 128x32
            int li = i*256 + tid, row = li >> 2, kc = (li & 3) << 3;
            *reinterpret_cast<uint4*>(As + row*LDA + kc) =
                *reinterpret_cast<const uint4*>(Ab + (size_t)(m0+row)*K + k0 + kc);
        }
        {                                           // B: 64x32
            int row = tid >> 2, kc = (tid & 3) << 3;
            *reinterpret_cast<uint4*>(Bs + row*LDA + kc) =
                *reinterpret_cast<const uint4*>(Bb + (size_t)(n0+row)*K + k0 + kc);
        }
        __syncthreads();
#pragma unroll
        for (int kk = 0; kk < 32; kk += 16) {
            wmma::fragment<wmma::matrix_a, 16, 16, 16, bf16, wmma::row_major> af[2];
            wmma::fragment<wmma::matrix_b, 16, 16, 16, bf16, wmma::col_major> bfr[2];
#pragma unroll
            for (int i = 0; i < 2; i++)
                wmma::load_matrix_sync(af[i], As + (wm + i*16)*LDA + kk, LDA);
#pragma unroll
            for (int j = 0; j < 2; j++)
                wmma::load_matrix_sync(bfr[j], Bs + (wn + j*16)*LDA + kk, LDA);
#pragma unroll
            for (int i = 0; i < 2; i++)
#pragma unroll
                for (int j = 0; j < 2; j++)
                    wmma::mma_sync(acc[i][j], af[i], bfr[j], acc[i][j]);
        }
    }
    __syncthreads();
#pragma unroll
    for (int i = 0; i < 2; i++)
#pragma unroll
        for (int j = 0; j < 2; j++)
            wmma::store_matrix_sync(Cs + (wm + i*16)*LDC + wn + j*16, acc[i][j],
                                    LDC, wmma::mem_row_major);
    __syncthreads();

    // per-thread epilogue: row = tid/2, col half = (tid&1)*32
    int row = tid >> 1, c0 = (tid & 1) * 32;
    int r = m0 + row;
    const float* cp = Cs + row*LDC + c0;

    if (mode == 0) {                       // QKV scatter (fp32 q/k/v)
        int b = r >> 12, n = r & (NS - 1);
        int part = n0 >> 8, h = (n0 >> 6) & 3;
        float scale = (part == 0) ? 0.125f : 1.0f;
        float* dst = (part == 0 ? g_q : (part == 1 ? g_k : g_v))
                   + (((size_t)b*NH + h)*NS + n)*DH + c0;
#pragma unroll
        for (int c = 0; c < 32; c++) dst[c] = cp[c] * scale;
    } else if (mode == 1) {                // pinv: scl*(sCoef*acc + aCoef*A)
        size_t ob = (size_t)bz * 65536;
#pragma unroll
        for (int c = 0; c < 32; c++) {
            int col = n0 + c0 + c;
            float v = sCoef * cp[c];
            if (aCoef != 0.0f) v += aCoef * __bfloat162float(Ab[(size_t)r*K + col]);
            v *= scl;
            bf16 hv = __float2bfloat16(v);
            if (outb)  outb [ob + (size_t)r*256 + col] = hv;
            if (outbT) outbT[ob + (size_t)col*256 + r] = hv;
        }
    } else if (mode == 2) {                // u^T
        size_t ob = (size_t)bz * (DH*NM);
#pragma unroll
        for (int c = 0; c < 32; c++)
            outbT[ob + (size_t)(c0 + c)*256 + r] = __float2bfloat16(cp[c]);
    } else if (mode == 3) {                // a1@u + conv residual -> bf16 oh
        int b = bz >> 2, h = bz & 3;
        size_t base = ((size_t)b*NS + r)*NI + h*64 + c0;
#pragma unroll
        for (int c = 0; c < 32; c++)
            g_ohb[base + c] = __float2bfloat16(cp[c] + g_ohf[base + c]);
    } else {                               // proj: out = acc + bias + x
        size_t base = (size_t)r * ND;
#pragma unroll
        for (int c = 0; c < 32; c++) {
            int col = n0 + c0 + c;
            outf[base + col] = cp[c] + bias[col] + xres[base + col];
        }
    }
}

// ---------------- LayerNorm -> bf16 -----------------------------------------
__global__ __launch_bounds__(128) void ln_kernel(
    const float* __restrict__ x, const float* __restrict__ g, const float* __restrict__ b)
{
    int row = blockIdx.x, t = threadIdx.x;
    float4 v4 = reinterpret_cast<const float4*>(x + (size_t)row*ND)[t];
    float s = v4.x + v4.y + v4.z + v4.w;
    __shared__ float r1[4], r2[4];
#pragma unroll
    for (int o = 16; o > 0; o >>= 1) s += __shfl_xor_sync(~0u, s, o);
    if ((t & 31) == 0) r1[t >> 5] = s;
    __syncthreads();
    float mu = (r1[0]+r1[1]+r1[2]+r1[3]) * (1.0f/ND);
    float dx = v4.x-mu, dy = v4.y-mu, dz = v4.z-mu, dw = v4.w-mu;
    float ss = dx*dx + dy*dy + dz*dz + dw*dw;
#pragma unroll
    for (int o = 16; o > 0; o >>= 1) ss += __shfl_xor_sync(~0u, ss, o);
    if ((t & 31) == 0) r2[t >> 5] = ss;
    __syncthreads();
    float inv = rsqrtf((r2[0]+r2[1]+r2[2]+r2[3]) * (1.0f/ND) + 1e-5f);
    float4 gv = reinterpret_cast<const float4*>(g)[t];
    float4 bv = reinterpret_cast<const float4*>(b)[t];
    uint2 o2;
    o2.x = pack_bf2(dx*inv*gv.x + bv.x, dy*inv*gv.y + bv.y);
    o2.y = pack_bf2(dz*inv*gv.z + bv.z, dw*inv*gv.w + bv.w);
    reinterpret_cast<uint2*>(g_xnb + (size_t)row*ND)[t] = o2;
}

// ---------------- weight transposes ------------------------------------------
__global__ void wqkvT_kernel(const float* __restrict__ w) {
    int idx = blockIdx.x * blockDim.x + threadIdx.x;
    int k = idx & 511, n = idx >> 9;
    g_wqkvT[idx] = __float2bfloat16(w[(size_t)k*768 + n]);
}
__global__ void woutT_kernel(const float* __restrict__ w) {
    int idx = blockIdx.x * blockDim.x + threadIdx.x;
    int k = idx & 255, n = idx >> 8;
    g_woutT[idx] = __float2bfloat16(w[(size_t)k*512 + n]);
}

// ---------------- landmarks ---------------------------------------------------
__global__ void landmark_kernel(const float* __restrict__ src, float* __restrict__ dst)
{
    int idx = blockIdx.x * blockDim.x + threadIdx.x;
    int d = idx & 63, j = (idx >> 6) & (NM - 1), bh = idx >> 14;
    const float* p = src + ((size_t)bh*NS + (size_t)j*16)*DH + d;
    float s = 0.f;
#pragma unroll
    for (int i = 0; i < 16; i++) s += p[(size_t)i*DH];
    dst[idx] = s * (1.0f/16.0f);
}

// ---------------- fused A@B^T + softmax(256) -> bf16 -------------------------
__global__ __launch_bounds__(256) void attn_sm256_kernel(
    const float* __restrict__ A, const float* __restrict__ Bm,
    bf16* __restrict__ O, int Ma)
{
    __shared__ __align__(16) float Qs[16][64];
    __shared__ float Bs[64][65];
    __shared__ __align__(16) float Ss[16][256];
    int bh = blockIdx.y, r0 = blockIdx.x * 16;
    const float* Abp = A + (size_t)bh*Ma*DH;
    const float* Bb = Bm + (size_t)bh*NM*DH;
    bf16* Ob = O + (size_t)bh*Ma*NM;
    int t = threadIdx.x;
    {
        int rr = t >> 4, c4 = (t & 15) << 2;
        *reinterpret_cast<float4*>(&Qs[rr][c4]) =
            *reinterpret_cast<const float4*>(Abp + (size_t)(r0+rr)*DH + c4);
    }
    int row = t >> 4, cb0 = t & 15;
    float acc[16];
    for (int cb = 0; cb < 4; cb++) {
        __syncthreads();
#pragma unroll
        for (int i = 0; i < 4; i++) {
            int fi = i*256 + t, rr = fi >> 4, c4 = (fi & 15) << 2;
            float4 bv = *reinterpret_cast<const float4*>(Bb + (size_t)(cb*64+rr)*DH + c4);
            Bs[rr][c4+0] = bv.x; Bs[rr][c4+1] = bv.y; Bs[rr][c4+2] = bv.z; Bs[rr][c4+3] = bv.w;
        }
        __syncthreads();
        float a0 = 0, a1 = 0, a2 = 0, a3 = 0;
#pragma unroll
        for (int k = 0; k < 64; k++) {
            float a = Qs[row][k];
            a0 += a * Bs[cb0][k];      a1 += a * Bs[cb0+16][k];
            a2 += a * Bs[cb0+32][k];   a3 += a * Bs[cb0+48][k];
        }
        acc[cb*4+0] = a0; acc[cb*4+1] = a1; acc[cb*4+2] = a2; acc[cb*4+3] = a3;
    }
    float mx = acc[0];
#pragma unroll
    for (int i = 1; i < 16; i++) mx = fmaxf(mx, acc[i]);
#pragma unroll
    for (int o = 8; o > 0; o >>= 1) mx = fmaxf(mx, __shfl_xor_sync(~0u, mx, o));
    float sum = 0.f;
#pragma unroll
    for (int i = 0; i < 16; i++) { acc[i] = __expf(acc[i] - mx); sum += acc[i]; }
#pragma unroll
    for (int o = 8; o > 0; o >>= 1) sum += __shfl_xor_sync(~0u, sum, o);
    float inv = 1.0f / sum;
#pragma unroll
    for (int i = 0; i < 16; i++) Ss[row][cb0 + 16*i] = acc[i] * inv;
    __syncthreads();
#pragma unroll
    for (int i = 0; i < 4; i++) {
        int fi = i*256 + t, rr = fi >> 6, c4 = (fi & 63) << 2;
        const float* sp = &Ss[rr][c4];
        uint2 o2 = { pack_bf2(sp[0], sp[1]), pack_bf2(sp[2], sp[3]) };
        *reinterpret_cast<uint2*>(Ob + (size_t)(r0+rr)*NM + c4) = o2;
    }
}

// ---------------- flash: w3^T = (softmax(ql@k^T) @ v)^T  (bf16) --------------
__global__ __launch_bounds__(256) void sim3_flash_kernel()
{
    __shared__ __align__(16) float Qs[16][64];
    __shared__ float Ks[64][65];
    __shared__ float Vs[64][65];
    __shared__ float Ps[16][64];
    int bh = blockIdx.y, r0 = blockIdx.x * 16;
    const float* Qb = g_ql + ((size_t)bh*NM + r0)*DH;
    const float* Kb = g_k + (size_t)bh*NS*DH;
    const float* Vb = g_v + (size_t)bh*NS*DH;
    int t = threadIdx.x, row = t >> 4, ln = t & 15;
    {
        int rr = t >> 4, c4 = (t & 15) << 2;
        *reinterpret_cast<float4*>(&Qs[rr][c4]) =
            *reinterpret_cast<const float4*>(Qb + (size_t)rr*DH + c4);
    }
    float Oa[4] = {0,0,0,0};
    float mrun = -1e30f, lrun = 0.f;
    for (int kt = 0; kt < NS/64; kt++) {
        __syncthreads();
#pragma unroll
        for (int i = 0; i < 4; i++) {
            int fi = i*256 + t, rr = fi >> 4, c4 = (fi & 15) << 2;
            float4 kv = *reinterpret_cast<const float4*>(Kb + (size_t)(kt*64+rr)*DH + c4);
            Ks[rr][c4+0] = kv.x; Ks[rr][c4+1] = kv.y; Ks[rr][c4+2] = kv.z; Ks[rr][c4+3] = kv.w;
            float4 vv = *reinterpret_cast<const float4*>(Vb + (size_t)(kt*64+rr)*DH + c4);
            Vs[rr][c4+0] = vv.x; Vs[rr][c4+1] = vv.y; Vs[rr][c4+2] = vv.z; Vs[rr][c4+3] = vv.w;
        }
        __syncthreads();
        float s0 = 0, s1 = 0, s2 = 0, s3 = 0;
#pragma unroll
        for (int k = 0; k < 64; k++) {
            float a = Qs[row][k];
            s0 += a * Ks[ln][k];    s1 += a * Ks[ln+16][k];
            s2 += a * Ks[ln+32][k]; s3 += a * Ks[ln+48][k];
        }
        float tm = fmaxf(fmaxf(s0, s1), fmaxf(s2, s3));
#pragma unroll
        for (int o = 8; o > 0; o >>= 1) tm = fmaxf(tm, __shfl_xor_sync(~0u, tm, o));
        float newm = fmaxf(mrun, tm);
        float corr = __expf(mrun - newm);
        float p0 = __expf(s0-newm), p1 = __expf(s1-newm), p2 = __expf(s2-newm), p3 = __expf(s3-newm);
        Ps[row][ln] = p0; Ps[row][ln+16] = p1; Ps[row][ln+32] = p2; Ps[row][ln+48] = p3;
        float ps = p0 + p1 + p2 + p3;
#pragma unroll
        for (int o = 8; o > 0; o >>= 1) ps += __shfl_xor_sync(~0u, ps, o);
        lrun = lrun * corr + ps;
        mrun = newm;
#pragma unroll
        for (int j = 0; j < 4; j++) Oa[j] *= corr;
        __syncthreads();
#pragma unroll
        for (int c = 0; c < 64; c++) {
            float p = Ps[row][c];
            Oa[0] += p * Vs[c][ln];    Oa[1] += p * Vs[c][ln+16];
            Oa[2] += p * Vs[c][ln+32]; Oa[3] += p * Vs[c][ln+48];
        }
    }
    float invl = 1.0f / lrun;
    int m = r0 + row;
    bf16* Wb = g_w3T + (size_t)bh*DH*NM;
#pragma unroll
    for (int j = 0; j < 4; j++)
        Wb[(size_t)(ln + 16*j)*NM + m] = __float2bfloat16(Oa[j] * invl);
}

// ---------------- pinv prep / init -------------------------------------------
__global__ void init_red_kernel() { g_red[0] = 0u; g_red[1] = 0u; }

__global__ void pinv_prep_kernel()
{
    int i = blockIdx.x * blockDim.x + threadIdx.x;
    int bh = i >> 8, r = i & 255;
    const bf16* A = g_a2b + (size_t)bh*NM*NM;
    float rs = 0.f, cs = 0.f;
    for (int j = 0; j < NM; j++) {
        rs += __bfloat162float(A[(size_t)r*NM + j]);
        cs += __bfloat162float(A[(size_t)j*NM + r]);
    }
    atomicMax(&g_red[0], __float_as_uint(rs));
    atomicMax(&g_red[1], __float_as_uint(cs));
}

__global__ void zinit_kernel()
{
    float inv = 1.0f / (__uint_as_float(g_red[0]) * __uint_as_float(g_red[1]));
    int idx = blockIdx.x * blockDim.x + threadIdx.x;
    int j = idx & 255, i = (idx >> 8) & 255, bh = idx >> 16;
    float a = __bfloat162float(g_a2b[idx]) * inv;
    bf16 h = __float2bfloat16(a);
    g_zAT[idx] = h;
    g_zA[((size_t)bh*NM + j)*NM + i] = h;
}

// ---------------- depthwise conv residual -> g_ohf ---------------------------
__global__ void conv_kernel(const float* __restrict__ w)
{
    int idx = blockIdx.x * blockDim.x + threadIdx.x;
    int c = idx & 255, n = (idx >> 8) & (NS - 1), b = idx >> 20;
    int h = c >> 6, d = c & 63;
    const float* vb = g_v + ((size_t)(b*NH + h)*NS)*DH + d;
    float s = 0.f;
#pragma unroll
    for (int k = 0; k < KW; k++) {
        int nn = n + k - KW/2;
        if (nn >= 0 && nn < NS) s += w[h*KW + k] * vb[(size_t)nn*DH];
    }
    g_ohf[idx] = s;
}

// ---------------- host launcher ------------------------------------------------
template <typename T>
static T* symp(T& sym) { void* p = nullptr; cudaGetSymbolAddress(&p, sym); return (T*)p; }

extern "C" void kernel_launch(void* const* d_in, const int* in_sizes, int n_in,
                              void* d_out, int out_size)
{
    const float* x     = (const float*)d_in[0];
    const float* ln_g  = (const float*)d_in[1];
    const float* ln_b  = (const float*)d_in[2];
    const float* w_qkv = (const float*)d_in[3];
    const float* w_out = (const float*)d_in[4];
    const float* b_out = (const float*)d_in[5];
    const float* w_res = (const float*)d_in[6];
    float* out = (float*)d_out;

    float* p_q  = symp(*g_q);  float* p_k = symp(*g_k);
    float* p_ql = symp(*g_ql); float* p_kl = symp(*g_kl);
    bf16* p_xnb = symp(*g_xnb);   bf16* p_wqkvT = symp(*g_wqkvT);
    bf16* p_woutT = symp(*g_woutT);
    bf16* p_a1b = symp(*g_a1b);   bf16* p_a2b = symp(*g_a2b);
    bf16* p_zA  = symp(*g_zA);    bf16* p_zAT = symp(*g_zAT);
    bf16* p_zB  = symp(*g_zB);    bf16* p_zBT = symp(*g_zBT);
    bf16* p_xz  = symp(*g_xz);    bf16* p_xzT = symp(*g_xzT);
    bf16* p_t1T = symp(*g_t1T);   bf16* p_t2T = symp(*g_t2T);
    bf16* p_w3T = symp(*g_w3T);   bf16* p_uT  = symp(*g_uT);
    bf16* p_ohb = symp(*g_ohb);

    const long long SM2 = 65536, SW = (long long)DH*NM;

    ln_kernel<<<NB*NS, 128>>>(x, ln_g, ln_b);
    wqkvT_kernel<<<768*512/256, 256>>>(w_qkv);
    woutT_kernel<<<512*256/256, 256>>>(w_out);

    // QKV: [32768,512] @ wqkvT^T -> q/k/v fp32
    gemm_wmma<<<dim3(12, 256, 1), 256, GEMM_DSMEM>>>(
        p_xnb, p_wqkvT, 512, 0, 0, 0, 0.f, 1.f, 1.f, nullptr, nullptr, nullptr, nullptr, nullptr);

    landmark_kernel<<<(NBH*NM*DH)/256, 256>>>(p_q, p_ql);
    landmark_kernel<<<(NBH*NM*DH)/256, 256>>>(p_k, p_kl);

    attn_sm256_kernel<<<dim3(NS/16, NBH), 256>>>(p_q,  p_kl, p_a1b, NS);
    attn_sm256_kernel<<<dim3(NM/16, NBH), 256>>>(p_ql, p_kl, p_a2b, NM);
    sim3_flash_kernel<<<dim3(NM/16, NBH), 256>>>();

    init_red_kernel<<<1, 1>>>();
    pinv_prep_kernel<<<32, 256>>>();
    zinit_kernel<<<(NBH*NM*NM)/256, 256>>>();

    bf16 *zc = p_zA, *zcT = p_zAT, *zn = p_zB, *znT = p_zBT;
    dim3 gsq(4, 2, NBH);
    for (int it = 0; it < 6; it++) {
        gemm_wmma<<<gsq, 256, GEMM_DSMEM>>>(p_a2b, zcT, 256, SM2, SM2, 1, 0.f, 1.f, 1.f,
                                            p_xz, p_xzT, nullptr, nullptr, nullptr);
        gemm_wmma<<<gsq, 256, GEMM_DSMEM>>>(p_xz, p_xzT, 256, SM2, SM2, 1, 7.f, -1.f, 1.f,
                                            nullptr, p_t1T, nullptr, nullptr, nullptr);
        gemm_wmma<<<gsq, 256, GEMM_DSMEM>>>(p_xz, p_t1T, 256, SM2, SM2, 1, 15.f, -1.f, 1.f,
                                            nullptr, p_t2T, nullptr, nullptr, nullptr);
        gemm_wmma<<<gsq, 256, GEMM_DSMEM>>>(zc, p_t2T, 256, SM2, SM2, 1, 13.f, -1.f, 0.25f,
                                            zn, znT, nullptr, nullptr, nullptr);
        bf16* t;
        t = zc; zc = zn; zn = t;
        t = zcT; zcT = znT; znT = t;
    }
    // u^T = (z @ w3)^T
    gemm_wmma<<<dim3(1, 2, NBH), 256, GEMM_DSMEM>>>(zc, p_w3T, 256, SM2, SW, 2, 0.f, 1.f, 1.f,
                                                    nullptr, p_uT, nullptr, nullptr, nullptr);
    // conv residual then oh = a1@u + conv
    conv_kernel<<<(NB*NS*NI)/256, 256>>>(w_res);
    gemm_wmma<<<dim3(1, 32, NBH), 256, GEMM_DSMEM>>>(p_a1b, p_uT, 256, (long long)NS*NM, SW, 3,
                                                     0.f, 1.f, 1.f, nullptr, nullptr, nullptr, nullptr, nullptr);
    // out = x + oh @ w_out + b
    gemm_wmma<<<dim3(8, 256, 1), 256, GEMM_DSMEM>>>(p_ohb, p_woutT, 256, 0, 0, 4,
                                                    0.f, 1.f, 1.f, nullptr, nullptr, out, b_out, x);
}